// round 1
// baseline (speedup 1.0000x reference)
#include <cuda_runtime.h>
#include <cuda_bf16.h>

// RoIPooling: crop_and_resize bilinear, POOL 7x7.
// feature_map: [B=8, H=64, W=64, C=256] fp32
// roi_bboxes:  [B=8, N=1000, 4] fp32 (y1,x1,y2,x2) normalized
// out:         [B, N, 7, 7, C] fp32
//
// One warp per output cell (box, py, px): 8*1000*49 = 392000 cells.
// Each warp handles all 256 channels as 64 float4 quads (2 per lane).

namespace {

constexpr int Hc = 64;
constexpr int Wc = 64;
constexpr int Cc = 256;          // channels
constexpr int CQ = Cc / 4;       // 64 float4 per row-position
constexpr int PH = 7;
constexpr int PW = 7;
constexpr int Bc = 8;
constexpr int Nc = 1000;
constexpr int NUM_CELLS = Bc * Nc * PH * PW;   // 392000
constexpr int WARPS_PER_BLOCK = 8;
constexpr int THREADS = WARPS_PER_BLOCK * 32;

__global__ __launch_bounds__(THREADS) void roi_pool_kernel(
    const float* __restrict__ fm,
    const float* __restrict__ boxes,
    float* __restrict__ out)
{
    const int gwarp = (blockIdx.x * WARPS_PER_BLOCK) + (threadIdx.x >> 5);
    if (gwarp >= NUM_CELLS) return;
    const int lane = threadIdx.x & 31;

    // Decode cell: cell = ((box * PH) + py) * PW + px
    const int px  = gwarp % PW;
    int tmp       = gwarp / PW;
    const int py  = tmp % PH;
    const int box = tmp / PH;          // 0 .. B*N-1 (batch-major, matches output layout)
    const int b   = box / Nc;

    // Box coords (16B aligned: 4 floats per box)
    const float4 bc = __ldg(reinterpret_cast<const float4*>(boxes) + box);
    const float y1 = bc.x, x1 = bc.y, y2 = bc.z, x2 = bc.w;

    // Sample coords (match jax reference ordering of ops)
    const float hm1 = (float)(Hc - 1);
    const float wm1 = (float)(Wc - 1);
    const float y = y1 * hm1 + (float)py * ((y2 - y1) * hm1 / (float)(PH - 1));
    const float x = x1 * wm1 + (float)px * ((x2 - x1) * wm1 / (float)(PW - 1));

    const float y0f = floorf(y);
    const float x0f = floorf(x);
    const float wy = y - y0f;
    const float wx = x - x0f;

    int y0 = (int)y0f;  y0 = min(max(y0, 0), Hc - 1);
    int x0 = (int)x0f;  x0 = min(max(x0, 0), Wc - 1);
    const int y1i = min(y0 + 1, Hc - 1);
    const int x1i = min(x0 + 1, Wc - 1);

    const bool valid = (y >= 0.0f) & (y <= hm1) & (x >= 0.0f) & (x <= wm1);

    // Base offsets in float4 units
    const float4* fm4 = reinterpret_cast<const float4*>(fm);
    const long long bbase = (long long)b * (Hc * Wc * CQ);
    const float4* p00 = fm4 + bbase + (long long)(y0  * Wc + x0 ) * CQ;
    const float4* p01 = fm4 + bbase + (long long)(y0  * Wc + x1i) * CQ;
    const float4* p10 = fm4 + bbase + (long long)(y1i * Wc + x0 ) * CQ;
    const float4* p11 = fm4 + bbase + (long long)(y1i * Wc + x1i) * CQ;

    float4* o4 = reinterpret_cast<float4*>(out) + (long long)gwarp * CQ;

    #pragma unroll
    for (int j = 0; j < 2; ++j) {
        const int q = lane + 32 * j;
        const float4 a = __ldg(p00 + q);
        const float4 bq = __ldg(p01 + q);
        const float4 c = __ldg(p10 + q);
        const float4 d = __ldg(p11 + q);

        float4 r;
        {
            float top, bot;
            top = a.x + (bq.x - a.x) * wx;
            bot = c.x + (d.x - c.x) * wx;
            r.x = top + (bot - top) * wy;
            top = a.y + (bq.y - a.y) * wx;
            bot = c.y + (d.y - c.y) * wx;
            r.y = top + (bot - top) * wy;
            top = a.z + (bq.z - a.z) * wx;
            bot = c.z + (d.z - c.z) * wx;
            r.z = top + (bot - top) * wy;
            top = a.w + (bq.w - a.w) * wx;
            bot = c.w + (d.w - c.w) * wx;
            r.w = top + (bot - top) * wy;
        }
        if (!valid) { r.x = 0.f; r.y = 0.f; r.z = 0.f; r.w = 0.f; }

        // Streaming store: keep the 401MB output from evicting the 33.5MB
        // feature map out of L2 (gathers depend on L2 hits).
        __stcs(o4 + q, r);
    }
}

} // namespace

extern "C" void kernel_launch(void* const* d_in, const int* in_sizes, int n_in,
                              void* d_out, int out_size) {
    const float* fm    = (const float*)d_in[0];
    const float* boxes = (const float*)d_in[1];
    float* out         = (float*)d_out;

    const int blocks = (NUM_CELLS + WARPS_PER_BLOCK - 1) / WARPS_PER_BLOCK;  // 49000
    roi_pool_kernel<<<blocks, THREADS>>>(fm, boxes, out);
}

// round 2
// speedup vs baseline: 1.2034x; 1.2034x over previous
#include <cuda_runtime.h>
#include <cuda_bf16.h>

// RoIPooling: crop_and_resize bilinear, POOL 7x7.
// feature_map: [B=8, H=64, W=64, C=256] fp32
// roi_bboxes:  [B=8, N=1000, 4] fp32 (y1,x1,y2,x2) normalized
// out:         [B, N, 7, 7, C] fp32
//
// R2: one warp per (box, py) ROW = 7 output cells. Amortizes box load,
// y-direction math, row base pointers and output base over 7 cells, cutting
// per-cell scalar issue overhead ~3x. Each px iteration: 8 front-batched
// LDG.128 (MLP=8) + 24 FFMA + 2 streaming STG.128.

namespace {

constexpr int Hc = 64;
constexpr int Wc = 64;
constexpr int Cc = 256;          // channels
constexpr int CQ = Cc / 4;       // 64 float4 per pixel
constexpr int PH = 7;
constexpr int PW = 7;
constexpr int Bc = 8;
constexpr int Nc = 1000;
constexpr int NUM_ROWS = Bc * Nc * PH;          // 56000 warps
constexpr int WARPS_PER_BLOCK = 8;
constexpr int THREADS = WARPS_PER_BLOCK * 32;

__global__ __launch_bounds__(THREADS) void roi_pool_kernel(
    const float* __restrict__ fm,
    const float* __restrict__ boxes,
    float* __restrict__ out)
{
    const int gwarp = (blockIdx.x * WARPS_PER_BLOCK) + (threadIdx.x >> 5);
    if (gwarp >= NUM_ROWS) return;
    const int lane = threadIdx.x & 31;

    // gwarp = box * PH + py
    const int py  = gwarp % PH;
    const int box = gwarp / PH;        // 0 .. B*N-1 (batch-major, matches output)
    const int b   = box / Nc;

    // Box coords (16B aligned)
    const float4 bc = __ldg(reinterpret_cast<const float4*>(boxes) + box);
    const float by1 = bc.x, bx1 = bc.y, by2 = bc.z, bx2 = bc.w;

    const float hm1 = (float)(Hc - 1);
    const float wm1 = (float)(Wc - 1);

    // ---- y math: once per warp (matches reference op order) ----
    const float y = by1 * hm1 + (float)py * ((by2 - by1) * hm1 / (float)(PH - 1));
    const float y0f = floorf(y);
    const float wy  = y - y0f;
    int y0 = (int)y0f;  y0 = min(max(y0, 0), Hc - 1);
    const int y1i = min(y0 + 1, Hc - 1);
    const bool valid_y = (y >= 0.0f) & (y <= hm1);

    const float4* fm4 = reinterpret_cast<const float4*>(fm);
    const long long bbase = (long long)b * (Hc * Wc * CQ);
    const float4* rowT = fm4 + bbase + (long long)(y0  * Wc) * CQ;  // top row
    const float4* rowB = fm4 + bbase + (long long)(y1i * Wc) * CQ;  // bottom row

    // ---- x constants: once per warp ----
    const float xbase = bx1 * wm1;
    const float dx    = (bx2 - bx1) * wm1 / (float)(PW - 1);

    // Output base for this row of 7 cells: cells are contiguous (PW*CQ quads)
    float4* o4 = reinterpret_cast<float4*>(out) + ((long long)gwarp * PW) * CQ;

    const int q0 = lane;        // quad indices handled by this lane
    const int q1 = lane + 32;

    #pragma unroll 1
    for (int px = 0; px < PW; ++px) {
        const float x   = xbase + (float)px * dx;
        const float x0f = floorf(x);
        const float wx  = x - x0f;
        int x0 = (int)x0f;  x0 = min(max(x0, 0), Wc - 1);
        const int x1i = min(x0 + 1, Wc - 1);
        const bool valid = valid_y & (x >= 0.0f) & (x <= wm1);

        const float4* p00 = rowT + x0  * CQ;
        const float4* p01 = rowT + x1i * CQ;
        const float4* p10 = rowB + x0  * CQ;
        const float4* p11 = rowB + x1i * CQ;

        // Front-batch all 8 loads (MLP = 8)
        const float4 a0 = __ldg(p00 + q0);
        const float4 b0 = __ldg(p01 + q0);
        const float4 c0 = __ldg(p10 + q0);
        const float4 d0 = __ldg(p11 + q0);
        const float4 a1 = __ldg(p00 + q1);
        const float4 b1 = __ldg(p01 + q1);
        const float4 c1 = __ldg(p10 + q1);
        const float4 d1 = __ldg(p11 + q1);

        float4 r0, r1;
        {
            float top, bot;
            top = a0.x + (b0.x - a0.x) * wx;  bot = c0.x + (d0.x - c0.x) * wx;
            r0.x = top + (bot - top) * wy;
            top = a0.y + (b0.y - a0.y) * wx;  bot = c0.y + (d0.y - c0.y) * wx;
            r0.y = top + (bot - top) * wy;
            top = a0.z + (b0.z - a0.z) * wx;  bot = c0.z + (d0.z - c0.z) * wx;
            r0.z = top + (bot - top) * wy;
            top = a0.w + (b0.w - a0.w) * wx;  bot = c0.w + (d0.w - c0.w) * wx;
            r0.w = top + (bot - top) * wy;

            top = a1.x + (b1.x - a1.x) * wx;  bot = c1.x + (d1.x - c1.x) * wx;
            r1.x = top + (bot - top) * wy;
            top = a1.y + (b1.y - a1.y) * wx;  bot = c1.y + (d1.y - c1.y) * wx;
            r1.y = top + (bot - top) * wy;
            top = a1.z + (b1.z - a1.z) * wx;  bot = c1.z + (d1.z - c1.z) * wx;
            r1.z = top + (bot - top) * wy;
            top = a1.w + (b1.w - a1.w) * wx;  bot = c1.w + (d1.w - c1.w) * wx;
            r1.w = top + (bot - top) * wy;
        }
        if (!valid) {
            r0.x = r0.y = r0.z = r0.w = 0.f;
            r1.x = r1.y = r1.z = r1.w = 0.f;
        }

        // Streaming stores: keep the 401MB output stream from evicting the
        // 33.5MB feature map out of L2 (gathers depend on L2 hits).
        float4* oc = o4 + px * CQ;
        __stcs(oc + q0, r0);
        __stcs(oc + q1, r1);
    }
}

} // namespace

extern "C" void kernel_launch(void* const* d_in, const int* in_sizes, int n_in,
                              void* d_out, int out_size) {
    const float* fm    = (const float*)d_in[0];
    const float* boxes = (const float*)d_in[1];
    float* out         = (float*)d_out;

    const int blocks = (NUM_ROWS + WARPS_PER_BLOCK - 1) / WARPS_PER_BLOCK;  // 7000
    roi_pool_kernel<<<blocks, THREADS>>>(fm, boxes, out);
}

// round 3
// speedup vs baseline: 1.2608x; 1.0477x over previous
#include <cuda_runtime.h>
#include <cuda_bf16.h>

// RoIPooling: crop_and_resize bilinear, POOL 7x7.
// feature_map: [B=8, H=64, W=64, C=256] fp32
// roi_bboxes:  [B=8, N=1000, 4] fp32 (y1,x1,y2,x2) normalized
// out:         [B, N, 7, 7, C] fp32
//
// R3: one warp per (box, py, channel-half). 112000 warps. Per px iteration:
// 4 front-batched LDG.128 + 12 FFMA chains + 1 STG.128. Half the in-flight
// registers of R2 -> 8 CTAs/SM occupancy to saturate L1tex wavefronts.
// All offsets 32-bit (fm = 8.4M float4, out = 100.4M float4 both < 2^31).

namespace {

constexpr int Hc = 64;
constexpr int Wc = 64;
constexpr int Cc = 256;          // channels
constexpr int CQ = Cc / 4;       // 64 float4 per pixel
constexpr int PH = 7;
constexpr int PW = 7;
constexpr int Bc = 8;
constexpr int Nc = 1000;
constexpr int NUM_WARPS = Bc * Nc * PH * 2;     // 112000 (2 channel-halves)
constexpr int WARPS_PER_BLOCK = 8;
constexpr int THREADS = WARPS_PER_BLOCK * 32;

__global__ __launch_bounds__(THREADS, 8) void roi_pool_kernel(
    const float* __restrict__ fm,
    const float* __restrict__ boxes,
    float* __restrict__ out)
{
    const int gwarp = (blockIdx.x * WARPS_PER_BLOCK) + (threadIdx.x >> 5);
    const int lane = threadIdx.x & 31;

    // gwarp = (box * PH + py) * 2 + half
    const int half = gwarp & 1;
    const int row  = gwarp >> 1;       // box * PH + py
    const int py   = row % PH;
    const int box  = row / PH;         // 0 .. B*N-1 (batch-major, matches output)
    const int b    = box / Nc;

    // Box coords (16B aligned)
    const float4 bc = __ldg(reinterpret_cast<const float4*>(boxes) + box);
    const float by1 = bc.x, bx1 = bc.y, by2 = bc.z, bx2 = bc.w;

    const float hm1 = (float)(Hc - 1);
    const float wm1 = (float)(Wc - 1);

    // ---- y math: once per warp (matches reference op order) ----
    const float y = by1 * hm1 + (float)py * ((by2 - by1) * hm1 / (float)(PH - 1));
    const float y0f = floorf(y);
    const float wy  = y - y0f;
    int y0 = (int)y0f;  y0 = min(max(y0, 0), Hc - 1);
    const int y1i = min(y0 + 1, Hc - 1);
    const bool valid_y = (y >= 0.0f) & (y <= hm1);

    // quad index within the pixel handled by this lane
    const int q = half * 32 + lane;

    // 32-bit float4 offsets
    const float4* fm4 = reinterpret_cast<const float4*>(fm);
    const int bbase   = b * (Hc * Wc * CQ);
    const int rowT    = bbase + y0  * (Wc * CQ) + q;   // top row, this lane's quad
    const int rowB    = bbase + y1i * (Wc * CQ) + q;   // bottom row

    // ---- x constants: once per warp ----
    const float xbase = bx1 * wm1;
    const float dx    = (bx2 - bx1) * wm1 / (float)(PW - 1);

    // Output offset (float4 units): row * (PW*CQ) + q, advancing CQ per px
    unsigned int oofs = (unsigned int)row * (PW * CQ) + q;
    float4* o4 = reinterpret_cast<float4*>(out);

    #pragma unroll 1
    for (int px = 0; px < PW; ++px) {
        const float x   = xbase + (float)px * dx;
        const float x0f = floorf(x);
        const float wx  = x - x0f;
        int x0 = (int)x0f;  x0 = min(max(x0, 0), Wc - 1);
        const int x1i = min(x0 + 1, Wc - 1);
        const bool valid = valid_y & (x >= 0.0f) & (x <= wm1);

        // Front-batch the 4 corner loads (MLP = 4 per warp, x8 warps/SMSP)
        const float4 a = __ldg(fm4 + rowT + x0  * CQ);
        const float4 bq= __ldg(fm4 + rowT + x1i * CQ);
        const float4 c = __ldg(fm4 + rowB + x0  * CQ);
        const float4 d = __ldg(fm4 + rowB + x1i * CQ);

        float4 r;
        {
            float top, bot;
            top = a.x + (bq.x - a.x) * wx;  bot = c.x + (d.x - c.x) * wx;
            r.x = top + (bot - top) * wy;
            top = a.y + (bq.y - a.y) * wx;  bot = c.y + (d.y - c.y) * wx;
            r.y = top + (bot - top) * wy;
            top = a.z + (bq.z - a.z) * wx;  bot = c.z + (d.z - c.z) * wx;
            r.z = top + (bot - top) * wy;
            top = a.w + (bq.w - a.w) * wx;  bot = c.w + (d.w - c.w) * wx;
            r.w = top + (bot - top) * wy;
        }
        if (!valid) { r.x = r.y = r.z = r.w = 0.f; }

        // Streaming store: keep the 401MB output stream from evicting the
        // 33.5MB feature map out of L2 (gathers depend on L2 hits).
        __stcs(o4 + oofs, r);
        oofs += CQ;
    }
}

} // namespace

extern "C" void kernel_launch(void* const* d_in, const int* in_sizes, int n_in,
                              void* d_out, int out_size) {
    const float* fm    = (const float*)d_in[0];
    const float* boxes = (const float*)d_in[1];
    float* out         = (float*)d_out;

    const int blocks = NUM_WARPS / WARPS_PER_BLOCK;  // 14000, exact
    roi_pool_kernel<<<blocks, THREADS>>>(fm, boxes, out);
}